// round 2
// baseline (speedup 1.0000x reference)
#include <cuda_runtime.h>
#include <cuda_bf16.h>

// Problem constants
#define HH   64
#define WW   128
#define CC   256
#define NPIX (HH * WW)          // 8192
#define NH   8
#define HD   32
#define C3   (3 * CC)           // 768
#define KK   7

// Scratch (device globals; no allocation allowed)
__device__ float g_qkv[NPIX * C3];   // 25 MB
__device__ float g_att[NPIX * CC];   // 8 MB

// ---------------------------------------------------------------------------
// Tiled fp32 GEMM with fused bias: C = A(MxK) * B(KxN) + bias(N)
// BM=BN=128, BK=16, 256 threads, 8x8 per-thread tile.
// Assumes M%128==0, N%128==0, K%16==0 (true for all three calls).
// ---------------------------------------------------------------------------
template <int BM, int BN, int BK, int TM, int TN>
__global__ __launch_bounds__(256, 2)
void sgemm_bias(const float* __restrict__ A, const float* __restrict__ B,
                const float* __restrict__ bias, float* __restrict__ C,
                int M, int N, int K)
{
    __shared__ float As[BM][BK + 1];   // +1 pad: conflict-free column reads
    __shared__ float Bs[BK][BN];

    const int tid = threadIdx.x;
    const int bx  = blockIdx.x;        // N tile
    const int by  = blockIdx.y;        // M tile

    const int tx = tid % (BN / TN);    // 0..15
    const int ty = tid / (BN / TN);    // 0..15

    // global->smem index precompute
    const int aRow  = tid / (BK / 4);  // 0..63
    const int aCol4 = tid % (BK / 4);  // 0..3
    const int bRow  = tid / (BN / 4);  // 0..7
    const int bCol4 = tid % (BN / 4);  // 0..31

    float acc[TM][TN];
#pragma unroll
    for (int i = 0; i < TM; i++)
#pragma unroll
        for (int j = 0; j < TN; j++) acc[i][j] = 0.0f;

    for (int k0 = 0; k0 < K; k0 += BK) {
        // Load A tile (BM x BK), 2 float4 per thread
#pragma unroll
        for (int it = 0; it < 2; it++) {
            int r = aRow + it * 64;
            float4 v = *(const float4*)&A[(size_t)(by * BM + r) * K + k0 + aCol4 * 4];
            As[r][aCol4 * 4 + 0] = v.x;
            As[r][aCol4 * 4 + 1] = v.y;
            As[r][aCol4 * 4 + 2] = v.z;
            As[r][aCol4 * 4 + 3] = v.w;
        }
        // Load B tile (BK x BN), 2 float4 per thread, coalesced
#pragma unroll
        for (int it = 0; it < 2; it++) {
            int r = bRow + it * 8;
            *(float4*)&Bs[r][bCol4 * 4] =
                *(const float4*)&B[(size_t)(k0 + r) * N + bx * BN + bCol4 * 4];
        }
        __syncthreads();

#pragma unroll
        for (int k = 0; k < BK; k++) {
            float rm[TM], rn[TN];
#pragma unroll
            for (int i = 0; i < TM; i++) rm[i] = As[ty * TM + i][k];
#pragma unroll
            for (int j = 0; j < TN; j += 4) {
                float4 v = *(const float4*)&Bs[k][tx * TN + j];
                rn[j] = v.x; rn[j + 1] = v.y; rn[j + 2] = v.z; rn[j + 3] = v.w;
            }
#pragma unroll
            for (int i = 0; i < TM; i++)
#pragma unroll
                for (int j = 0; j < TN; j++)
                    acc[i][j] = fmaf(rm[i], rn[j], acc[i][j]);
        }
        __syncthreads();
    }

    // Epilogue: bias add + float4 stores
#pragma unroll
    for (int i = 0; i < TM; i++) {
        int row = by * BM + ty * TM + i;
#pragma unroll
        for (int j = 0; j < TN; j += 4) {
            int col = bx * BN + tx * TN + j;
            float4 o;
            o.x = acc[i][j + 0] + bias[col + 0];
            o.y = acc[i][j + 1] + bias[col + 1];
            o.z = acc[i][j + 2] + bias[col + 2];
            o.w = acc[i][j + 3] + bias[col + 3];
            *(float4*)&C[(size_t)row * N + col] = o;
        }
    }
}

// ---------------------------------------------------------------------------
// 2D neighborhood attention (7x7), one block = 8x8 pixel tile x 1 head.
// K/V window (up to 14x14 pixels x 32 dims) staged in dynamic smem.
// One warp per tile row; lane = head-dim; butterfly-reduced dot products.
// ---------------------------------------------------------------------------
__global__ __launch_bounds__(256, 1)
void na_attn(const float* __restrict__ qkv, float* __restrict__ out)
{
    extern __shared__ float sm[];

    const int c0   = blockIdx.x * 8;
    const int r0   = blockIdx.y * 8;
    const int head = blockIdx.z;

    const int rlo = max(r0 - 3, 0);
    const int rhi = min(r0 + 10, HH - 1);
    const int nr  = rhi - rlo + 1;
    const int clo = max(c0 - 3, 0);
    const int chi = min(c0 + 10, WW - 1);
    const int nc  = chi - clo + 1;
    const int npx = nr * nc;

    float* sK = sm;
    float* sV = sm + npx * HD;

    const int tid = threadIdx.x;

    // Cooperative load of K and V window for this head (float4 per chunk)
    for (int t = tid; t < npx * (HD / 4); t += 256) {
        int p = t >> 3;            // pixel within window
        int f = t & 7;             // float4 index within 32 dims
        int gy = rlo + p / nc;
        int gx = clo + p % nc;
        const float* base = qkv + (size_t)(gy * WW + gx) * C3 + head * HD;
        *(float4*)&sK[p * HD + f * 4] = *(const float4*)(base + CC + f * 4);
        *(float4*)&sV[p * HD + f * 4] = *(const float4*)(base + 2 * CC + f * 4);
    }
    __syncthreads();

    const int warp = tid >> 5;
    const int lane = tid & 31;
    const int gy   = r0 + warp;
    const float scale = 0.17677669529663687f;   // 1/sqrt(32)

    const int sy = min(max(gy - 3, 0), HH - KK) - rlo;

    for (int lx = 0; lx < 8; lx++) {
        const int gx = c0 + lx;
        float qv = qkv[(size_t)(gy * WW + gx) * C3 + head * HD + lane] * scale;
        const int sx = min(max(gx - 3, 0), WW - KK) - clo;

        // Pass 1: 49 dot products via butterfly reductions (ILP across nbrs)
        float sc[KK * KK];
#pragma unroll
        for (int p = 0; p < KK; p++) {
#pragma unroll
            for (int q = 0; q < KK; q++) {
                float s = qv * sK[((sy + p) * nc + (sx + q)) * HD + lane];
                s += __shfl_xor_sync(0xffffffffu, s, 16);
                s += __shfl_xor_sync(0xffffffffu, s, 8);
                s += __shfl_xor_sync(0xffffffffu, s, 4);
                s += __shfl_xor_sync(0xffffffffu, s, 2);
                s += __shfl_xor_sync(0xffffffffu, s, 1);
                sc[p * KK + q] = s;
            }
        }

        float m = sc[0];
#pragma unroll
        for (int i = 1; i < KK * KK; i++) m = fmaxf(m, sc[i]);

        // Pass 2: exp + weighted V accumulation (lane owns one head-dim)
        float l = 0.0f, acc = 0.0f;
#pragma unroll
        for (int p = 0; p < KK; p++) {
#pragma unroll
            for (int q = 0; q < KK; q++) {
                float e = __expf(sc[p * KK + q] - m);
                l += e;
                acc = fmaf(e, sV[((sy + p) * nc + (sx + q)) * HD + lane], acc);
            }
        }

        out[(size_t)(gy * WW + gx) * CC + head * HD + lane] = acc / l;
    }
}

// ---------------------------------------------------------------------------
// kernel_launch
// ---------------------------------------------------------------------------
extern "C" void kernel_launch(void* const* d_in, const int* in_sizes, int n_in,
                              void* d_out, int out_size)
{
    const float* x      = (const float*)d_in[0];
    const float* w_qkv  = (const float*)d_in[1];
    const float* b_qkv  = (const float*)d_in[2];
    const float* w_proj = (const float*)d_in[3];
    const float* b_proj = (const float*)d_in[4];
    float* out = (float*)d_out;

    float* qkv;
    float* att;
    cudaGetSymbolAddress((void**)&qkv, g_qkv);
    cudaGetSymbolAddress((void**)&att, g_att);

    // 1) QKV projection: [8192,256] @ [256,768] + b
    {
        dim3 grid(C3 / 128, NPIX / 128);
        sgemm_bias<128, 128, 16, 8, 8><<<grid, 256>>>(x, w_qkv, b_qkv, qkv,
                                                      NPIX, C3, CC);
    }

    // 2) Neighborhood attention
    {
        const int smem = 2 * 14 * 14 * HD * (int)sizeof(float);  // 50176 B
        cudaFuncSetAttribute(na_attn, cudaFuncAttributeMaxDynamicSharedMemorySize,
                             smem);
        dim3 grid(WW / 8, HH / 8, NH);
        na_attn<<<grid, 256, smem>>>(qkv, att);
    }

    // 3) Output projection: [8192,256] @ [256,256] + b
    {
        dim3 grid(CC / 128, NPIX / 128);
        sgemm_bias<128, 128, 16, 8, 8><<<grid, 256>>>(att, w_proj, b_proj, out,
                                                      NPIX, CC, CC);
    }
}

// round 3
// speedup vs baseline: 1.3048x; 1.3048x over previous
#include <cuda_runtime.h>
#include <cuda_bf16.h>

// Problem constants
#define HH   64
#define WW   128
#define CC   256
#define NPIX (HH * WW)          // 8192
#define NH   8
#define HD   32
#define C3   (3 * CC)           // 768
#define KK   7

// Scratch (device globals; no allocation allowed)
__device__ float g_qkv[NPIX * C3];   // 25 MB
__device__ float g_att[NPIX * CC];   // 8 MB

// ---------------------------------------------------------------------------
// Tiled fp32 GEMM with fused bias: C = A(MxK) * B(KxN) + bias(N)
// BM=BN=128, BK=16, 256 threads, 8x8 per-thread tile.
// A tile stored transposed in smem (Ast[k][m], stride 132) so fragment loads
// are LDS.128 broadcasts. Register+smem double-buffering hides LDG latency.
// Assumes M%128==0, N%128==0, K%32==0.
// ---------------------------------------------------------------------------
#define BM 128
#define BN 128
#define BK 16
#define TM 8
#define TN 8
#define LDA (BM + 4)   // 132: 2-way (not 8-way) STS conflicts on transpose store

__global__ __launch_bounds__(256, 2)
void sgemm_bias(const float* __restrict__ A, const float* __restrict__ B,
                const float* __restrict__ bias, float* __restrict__ C,
                int M, int N, int K)
{
    __shared__ float Ast[2][BK * LDA];
    __shared__ float Bs [2][BK * BN];

    const int tid = threadIdx.x;
    const int bx  = blockIdx.x;        // N tile
    const int by  = blockIdx.y;        // M tile

    const int tx = tid % (BN / TN);    // 0..15
    const int ty = tid / (BN / TN);    // 0..15

    // A load mapping: float4 along K. 128 rows x 4 float4 = 512 -> 2 iters
    const int aRow  = tid >> 2;        // 0..63
    const int aCol4 = tid & 3;         // 0..3
    // B load mapping: 16 rows x 32 float4 = 512 -> 2 iters
    const int bRow  = tid >> 5;        // 0..7
    const int bCol4 = tid & 31;        // 0..31

    const float* Ag = A + (size_t)(by * BM) * K;
    const float* Bg = B + bx * BN;

    float4 aR[2], bR[2];

    // ---- prologue: load tile 0 ----
#pragma unroll
    for (int it = 0; it < 2; it++) {
        aR[it] = *(const float4*)&Ag[(size_t)(aRow + it * 64) * K + aCol4 * 4];
        bR[it] = *(const float4*)&Bg[(size_t)(bRow + it * 8) * N + bCol4 * 4];
    }
#pragma unroll
    for (int it = 0; it < 2; it++) {
        int r = aRow + it * 64;
        int k = aCol4 * 4;
        Ast[0][(k + 0) * LDA + r] = aR[it].x;
        Ast[0][(k + 1) * LDA + r] = aR[it].y;
        Ast[0][(k + 2) * LDA + r] = aR[it].z;
        Ast[0][(k + 3) * LDA + r] = aR[it].w;
        *(float4*)&Bs[0][(bRow + it * 8) * BN + bCol4 * 4] = bR[it];
    }
    __syncthreads();

    float acc[TM][TN];
#pragma unroll
    for (int i = 0; i < TM; i++)
#pragma unroll
        for (int j = 0; j < TN; j++) acc[i][j] = 0.0f;

    const int nIter = K / BK;
    int s = 0;

    for (int i = 0; i < nIter; i++) {
        // prefetch next tile into registers (latency hidden under compute)
        if (i + 1 < nIter) {
            int k0 = (i + 1) * BK;
#pragma unroll
            for (int it = 0; it < 2; it++) {
                aR[it] = *(const float4*)&Ag[(size_t)(aRow + it * 64) * K + k0 + aCol4 * 4];
                bR[it] = *(const float4*)&Bg[(size_t)(k0 + bRow + it * 8) * N + bCol4 * 4];
            }
        }

        // compute on stage s
#pragma unroll
        for (int k = 0; k < BK; k++) {
            float4 m0 = *(const float4*)&Ast[s][k * LDA + ty * TM];
            float4 m1 = *(const float4*)&Ast[s][k * LDA + ty * TM + 4];
            float4 n0 = *(const float4*)&Bs [s][k * BN  + tx * TN];
            float4 n1 = *(const float4*)&Bs [s][k * BN  + tx * TN + 4];
            float rm[TM] = {m0.x, m0.y, m0.z, m0.w, m1.x, m1.y, m1.z, m1.w};
            float rn[TN] = {n0.x, n0.y, n0.z, n0.w, n1.x, n1.y, n1.z, n1.w};
#pragma unroll
            for (int ii = 0; ii < TM; ii++)
#pragma unroll
                for (int jj = 0; jj < TN; jj++)
                    acc[ii][jj] = fmaf(rm[ii], rn[jj], acc[ii][jj]);
        }

        // store next tile into the other stage
        if (i + 1 < nIter) {
            int ns = s ^ 1;
#pragma unroll
            for (int it = 0; it < 2; it++) {
                int r = aRow + it * 64;
                int k = aCol4 * 4;
                Ast[ns][(k + 0) * LDA + r] = aR[it].x;
                Ast[ns][(k + 1) * LDA + r] = aR[it].y;
                Ast[ns][(k + 2) * LDA + r] = aR[it].z;
                Ast[ns][(k + 3) * LDA + r] = aR[it].w;
                *(float4*)&Bs[ns][(bRow + it * 8) * BN + bCol4 * 4] = bR[it];
            }
            __syncthreads();
        }
        s ^= 1;
    }

    // Epilogue: bias add + float4 stores
#pragma unroll
    for (int i = 0; i < TM; i++) {
        int row = by * BM + ty * TM + i;
#pragma unroll
        for (int j = 0; j < TN; j += 4) {
            int col = bx * BN + tx * TN + j;
            float4 o;
            o.x = acc[i][j + 0] + bias[col + 0];
            o.y = acc[i][j + 1] + bias[col + 1];
            o.z = acc[i][j + 2] + bias[col + 2];
            o.w = acc[i][j + 3] + bias[col + 3];
            *(float4*)&C[(size_t)row * N + col] = o;
        }
    }
}

// ---------------------------------------------------------------------------
// 2D neighborhood attention (7x7), one block = 8x8 pixel tile x 1 head.
// K/V window (up to 14x14 pixels x 32 dims) staged in dynamic smem.
// Warp = one pixel row; 8 lanes per pixel (lane owns 4 head-dims, float4),
// 4 pixels processed concurrently per warp, 2 rounds.
// Dot products: 4 FMA + 3-shuffle butterfly within the 8-lane group.
// ---------------------------------------------------------------------------
__global__ __launch_bounds__(256, 1)
void na_attn(const float* __restrict__ qkv, float* __restrict__ out)
{
    extern __shared__ float sm[];

    const int c0   = blockIdx.x * 8;
    const int r0   = blockIdx.y * 8;
    const int head = blockIdx.z;

    const int rlo = max(r0 - 3, 0);
    const int rhi = min(r0 + 10, HH - 1);
    const int nr  = rhi - rlo + 1;
    const int clo = max(c0 - 3, 0);
    const int chi = min(c0 + 10, WW - 1);
    const int nc  = chi - clo + 1;
    const int npx = nr * nc;

    float* sK = sm;
    float* sV = sm + npx * HD;

    const int tid = threadIdx.x;

    // Cooperative load of K and V window for this head (float4 chunks)
    for (int t = tid; t < npx * (HD / 4); t += 256) {
        int p = t >> 3;            // pixel within window
        int f = t & 7;             // float4 index within 32 dims
        int gy = rlo + p / nc;
        int gx = clo + p % nc;
        const float* base = qkv + (size_t)(gy * WW + gx) * C3 + head * HD;
        *(float4*)&sK[p * HD + f * 4] = *(const float4*)(base + CC + f * 4);
        *(float4*)&sV[p * HD + f * 4] = *(const float4*)(base + 2 * CC + f * 4);
    }
    __syncthreads();

    const int warp = tid >> 5;
    const int lane = tid & 31;
    const int sub  = lane >> 3;    // pixel-in-group 0..3
    const int l8   = lane & 7;     // float4 slot within 32 dims
    const int gy   = r0 + warp;
    const float scale = 0.17677669529663687f;   // 1/sqrt(32)

    const int sy = min(max(gy - 3, 0), HH - KK) - rlo;

#pragma unroll
    for (int t = 0; t < 2; t++) {
        const int gx = c0 + t * 4 + sub;
        const size_t pix = (size_t)(gy * WW + gx);

        float4 q4 = *(const float4*)&qkv[pix * C3 + head * HD + l8 * 4];
        q4.x *= scale; q4.y *= scale; q4.z *= scale; q4.w *= scale;

        const int sx = min(max(gx - 3, 0), WW - KK) - clo;
        const int base = (sy * nc + sx) * HD + l8 * 4;

        // Pass 1: 49 dot products (4 FMA + 3-shuffle butterfly each)
        float sc[KK * KK];
#pragma unroll
        for (int p = 0; p < KK; p++) {
#pragma unroll
            for (int q = 0; q < KK; q++) {
                const float4 k4 = *(const float4*)&sK[base + (p * nc + q) * HD];
                float s = q4.x * k4.x;
                s = fmaf(q4.y, k4.y, s);
                s = fmaf(q4.z, k4.z, s);
                s = fmaf(q4.w, k4.w, s);
                s += __shfl_xor_sync(0xffffffffu, s, 4);
                s += __shfl_xor_sync(0xffffffffu, s, 2);
                s += __shfl_xor_sync(0xffffffffu, s, 1);
                sc[p * KK + q] = s;
            }
        }

        float m = sc[0];
#pragma unroll
        for (int i = 1; i < KK * KK; i++) m = fmaxf(m, sc[i]);

        // Pass 2: exp + weighted V accumulation (lane owns 4 head-dims)
        float l = 0.0f;
        float4 acc = make_float4(0.f, 0.f, 0.f, 0.f);
#pragma unroll
        for (int p = 0; p < KK; p++) {
#pragma unroll
            for (int q = 0; q < KK; q++) {
                const float e = __expf(sc[p * KK + q] - m);
                l += e;
                const float4 v4 = *(const float4*)&sV[base + (p * nc + q) * HD];
                acc.x = fmaf(e, v4.x, acc.x);
                acc.y = fmaf(e, v4.y, acc.y);
                acc.z = fmaf(e, v4.z, acc.z);
                acc.w = fmaf(e, v4.w, acc.w);
            }
        }

        const float inv = 1.0f / l;
        float4 o;
        o.x = acc.x * inv; o.y = acc.y * inv; o.z = acc.z * inv; o.w = acc.w * inv;
        *(float4*)&out[pix * CC + head * HD + l8 * 4] = o;
    }
}

// ---------------------------------------------------------------------------
// kernel_launch
// ---------------------------------------------------------------------------
extern "C" void kernel_launch(void* const* d_in, const int* in_sizes, int n_in,
                              void* d_out, int out_size)
{
    const float* x      = (const float*)d_in[0];
    const float* w_qkv  = (const float*)d_in[1];
    const float* b_qkv  = (const float*)d_in[2];
    const float* w_proj = (const float*)d_in[3];
    const float* b_proj = (const float*)d_in[4];
    float* out = (float*)d_out;

    float* qkv;
    float* att;
    cudaGetSymbolAddress((void**)&qkv, g_qkv);
    cudaGetSymbolAddress((void**)&att, g_att);

    // 1) QKV projection: [8192,256] @ [256,768] + b
    {
        dim3 grid(C3 / BN, NPIX / BM);
        sgemm_bias<<<grid, 256>>>(x, w_qkv, b_qkv, qkv, NPIX, C3, CC);
    }

    // 2) Neighborhood attention
    {
        const int smem = 2 * 14 * 14 * HD * (int)sizeof(float);  // 50176 B
        cudaFuncSetAttribute(na_attn, cudaFuncAttributeMaxDynamicSharedMemorySize,
                             smem);
        dim3 grid(WW / 8, HH / 8, NH);
        na_attn<<<grid, 256, smem>>>(qkv, att);
    }

    // 3) Output projection: [8192,256] @ [256,256] + b
    {
        dim3 grid(CC / BN, NPIX / BM);
        sgemm_bias<<<grid, 256>>>(att, w_proj, b_proj, out, NPIX, CC, CC);
    }
}

// round 5
// speedup vs baseline: 2.1614x; 1.6564x over previous
#include <cuda_runtime.h>
#include <cuda_bf16.h>
#include <cstdint>

// Problem constants
#define HH   64
#define WW   128
#define CC   256
#define NPIX (HH * WW)          // 8192
#define NH   8
#define HD   32
#define C3   (3 * CC)           // 768
#define KK   7

// ---------------------------------------------------------------------------
// Scratch (device globals; no allocation allowed)
// ---------------------------------------------------------------------------
__device__ __align__(16) float         g_qkv[NPIX * C3];       // 25 MB
__device__ __align__(16) __nv_bfloat16 g_xh[NPIX * CC];
__device__ __align__(16) __nv_bfloat16 g_xl[NPIX * CC];
__device__ __align__(16) __nv_bfloat16 g_wqkvT_h[C3 * CC];
__device__ __align__(16) __nv_bfloat16 g_wqkvT_l[C3 * CC];
__device__ __align__(16) __nv_bfloat16 g_wprojT_h[CC * CC];
__device__ __align__(16) __nv_bfloat16 g_wprojT_l[CC * CC];
__device__ __align__(16) __nv_bfloat16 g_atth[NPIX * CC];
__device__ __align__(16) __nv_bfloat16 g_attl[NPIX * CC];

// ---------------------------------------------------------------------------
// PTX helpers (baseline ISA only: mma.sync / ldmatrix / cp.async)
// ---------------------------------------------------------------------------
__device__ __forceinline__ uint32_t smem_u32(const void* p) {
    uint32_t a;
    asm("{ .reg .u64 t; cvta.to.shared.u64 t, %1; cvt.u32.u64 %0, t; }"
        : "=r"(a) : "l"(p));
    return a;
}

__device__ __forceinline__ void cp_async16(uint32_t saddr, const void* gptr) {
    asm volatile("cp.async.cg.shared.global [%0], [%1], 16;"
                 :: "r"(saddr), "l"(gptr) : "memory");
}

__device__ __forceinline__ void ldsm_x4(uint32_t* r, uint32_t addr) {
    asm volatile("ldmatrix.sync.aligned.m8n8.x4.shared.b16 {%0,%1,%2,%3}, [%4];"
                 : "=r"(r[0]), "=r"(r[1]), "=r"(r[2]), "=r"(r[3]) : "r"(addr));
}

__device__ __forceinline__ void mma_16816(float* c, const uint32_t* a,
                                          const uint32_t* b) {
    asm volatile(
        "mma.sync.aligned.m16n8k16.row.col.f32.bf16.bf16.f32 "
        "{%0,%1,%2,%3}, {%4,%5,%6,%7}, {%8,%9}, {%0,%1,%2,%3};"
        : "+f"(c[0]), "+f"(c[1]), "+f"(c[2]), "+f"(c[3])
        : "r"(a[0]), "r"(a[1]), "r"(a[2]), "r"(a[3]), "r"(b[0]), "r"(b[1]));
}

// ---------------------------------------------------------------------------
// Prep kernels: fp32 -> bf16 hi/lo split (and transposed variant for weights)
// ---------------------------------------------------------------------------
__global__ void split_f32(const float* __restrict__ x,
                          __nv_bfloat16* __restrict__ h,
                          __nv_bfloat16* __restrict__ l, int n)
{
    int i = blockIdx.x * 256 + threadIdx.x;
    if (i < n) {
        float v = x[i];
        __nv_bfloat16 hi = __float2bfloat16(v);
        h[i] = hi;
        l[i] = __float2bfloat16(v - __bfloat162float(hi));
    }
}

// W [Kd][Nd] row-major -> T [Nd][Kd] hi/lo bf16 (K-major "B" operand)
__global__ void transpose_split(const float* __restrict__ W,
                                __nv_bfloat16* __restrict__ h,
                                __nv_bfloat16* __restrict__ l, int Kd, int Nd)
{
    int i = blockIdx.x * 256 + threadIdx.x;
    if (i < Kd * Nd) {
        int n = i / Kd, k = i % Kd;
        float v = W[(size_t)k * Nd + n];
        __nv_bfloat16 hi = __float2bfloat16(v);
        h[(size_t)n * Kd + k] = hi;
        l[(size_t)n * Kd + k] = __float2bfloat16(v - __bfloat162float(hi));
    }
}

// ---------------------------------------------------------------------------
// mma.sync bf16-split GEMM: C[M,N] = (Ah+Al)[M,K] @ (Bh+Bl)[N,K]^T + bias
// 3-term: Ah@Bh + Ah@Bl + Al@Bh. CTA tile 128x128, 8 warps (2M x 4N),
// warp tile 64x32. K chunks of 64, 2-stage cp.async pipeline.
// smem rows padded to 72 bf16 (144 B) -> conflict-free ldmatrix.
// ---------------------------------------------------------------------------
#define BKC 64
#define LDKB 144                         // padded row bytes (72 bf16)
#define BUF_BYTES (128 * LDKB)           // 18432
#define STAGE_BYTES (4 * BUF_BYTES)      // 73728  (Ah|Al|Bh|Bl)
#define GT_SMEM (2 * STAGE_BYTES)        // 147456

__global__ __launch_bounds__(256, 1)
void gemm_mma(const __nv_bfloat16* __restrict__ Ah, const __nv_bfloat16* __restrict__ Al,
              const __nv_bfloat16* __restrict__ Bh, const __nv_bfloat16* __restrict__ Bl,
              const float* __restrict__ bias, float* __restrict__ C, int N, int K)
{
    extern __shared__ char smem[];
    const uint32_t sb = smem_u32(smem);
    const int tid  = threadIdx.x;
    const int wid  = tid >> 5;
    const int lane = tid & 31;
    const int warpM = wid & 1;           // 0..1
    const int warpN = wid >> 1;          // 0..3

    const size_t aBase = (size_t)blockIdx.y * 128 * K;
    const size_t bBase = (size_t)blockIdx.x * 128 * K;
    const int nch = K / BKC;

    // ---- async chunk loader: 4 buffers x 128 rows x 64 bf16 ----
    auto issue_chunk = [&](int c) {
        const uint32_t st = sb + (uint32_t)(c & 1) * STAGE_BYTES;
        const int k0 = c * BKC;
#pragma unroll
        for (int i = 0; i < 4; i++) {
            const int idx = i * 256 + tid;
            const int r = idx >> 3, f = idx & 7;
            const uint32_t so = (uint32_t)r * LDKB + (uint32_t)f * 16;
            const size_t ga = aBase + (size_t)r * K + k0 + f * 8;
            const size_t gb = bBase + (size_t)r * K + k0 + f * 8;
            cp_async16(st + 0 * BUF_BYTES + so, Ah + ga);
            cp_async16(st + 1 * BUF_BYTES + so, Al + ga);
            cp_async16(st + 2 * BUF_BYTES + so, Bh + gb);
            cp_async16(st + 3 * BUF_BYTES + so, Bl + gb);
        }
        asm volatile("cp.async.commit_group;" ::: "memory");
    };

    float acc[4][4][4];
#pragma unroll
    for (int i = 0; i < 4; i++)
#pragma unroll
        for (int j = 0; j < 4; j++)
#pragma unroll
            for (int t = 0; t < 4; t++) acc[i][j][t] = 0.0f;

    issue_chunk(0);

    for (int c = 0; c < nch; c++) {
        if (c + 1 < nch) {
            issue_chunk(c + 1);
            asm volatile("cp.async.wait_group 1;" ::: "memory");
        } else {
            asm volatile("cp.async.wait_group 0;" ::: "memory");
        }
        __syncthreads();

        const uint32_t st  = sb + (uint32_t)(c & 1) * STAGE_BYTES;
        const uint32_t sA0 = st;
        const uint32_t sA1 = st + 1 * BUF_BYTES;
        const uint32_t sB0 = st + 2 * BUF_BYTES;
        const uint32_t sB1 = st + 3 * BUF_BYTES;

        // ldmatrix lane address components
        const int arow  = warpM * 64 + (lane & 15);
        const int bro   = warpN * 32 + (lane & 7) + ((lane >> 4) << 3);
        const uint32_t acolL = (uint32_t)((lane >> 4) * 16);
        const uint32_t bcolL = (uint32_t)(((lane >> 3) & 1) * 16);

#pragma unroll
        for (int ks = 0; ks < 4; ks++) {
            const uint32_t kb = (uint32_t)ks * 32;

            uint32_t ah[4][4], al[4][4];
#pragma unroll
            for (int ma = 0; ma < 4; ma++) {
                const uint32_t ad = (uint32_t)(arow + ma * 16) * LDKB + kb + acolL;
                ldsm_x4(ah[ma], sA0 + ad);
                ldsm_x4(al[ma], sA1 + ad);
            }

            uint32_t bh[4][2], bl[4][2];
#pragma unroll
            for (int g = 0; g < 2; g++) {
                const uint32_t bd = (uint32_t)(bro + g * 16) * LDKB + kb + bcolL;
                uint32_t t0[4], t1[4];
                ldsm_x4(t0, sB0 + bd);
                ldsm_x4(t1, sB1 + bd);
                bh[2 * g][0] = t0[0]; bh[2 * g][1] = t0[1];
                bh[2 * g + 1][0] = t0[2]; bh[2 * g + 1][1] = t0[3];
                bl[2 * g][0] = t1[0]; bl[2 * g][1] = t1[1];
                bl[2 * g + 1][0] = t1[2]; bl[2 * g + 1][1] = t1[3];
            }

#pragma unroll
            for (int ma = 0; ma < 4; ma++)
#pragma unroll
                for (int na = 0; na < 4; na++) {
                    mma_16816(acc[ma][na], ah[ma], bh[na]);
                    mma_16816(acc[ma][na], ah[ma], bl[na]);
                    mma_16816(acc[ma][na], al[ma], bh[na]);
                }
        }
        __syncthreads();
    }

    // ---- epilogue: bias + store (float2 per fragment row) ----
    const int row0 = blockIdx.y * 128 + warpM * 64 + (lane >> 2);
    const int col0 = blockIdx.x * 128 + warpN * 32 + (lane & 3) * 2;
#pragma unroll
    for (int na = 0; na < 4; na++) {
        const int cc = col0 + na * 8;
        const float2 b2 = *(const float2*)&bias[cc];
#pragma unroll
        for (int ma = 0; ma < 4; ma++) {
            const int r = row0 + ma * 16;
            float2 o0, o1;
            o0.x = acc[ma][na][0] + b2.x;
            o0.y = acc[ma][na][1] + b2.y;
            o1.x = acc[ma][na][2] + b2.x;
            o1.y = acc[ma][na][3] + b2.y;
            *(float2*)&C[(size_t)r * N + cc]       = o0;
            *(float2*)&C[(size_t)(r + 8) * N + cc] = o1;
        }
    }
}

// ---------------------------------------------------------------------------
// 2D neighborhood attention (7x7), one block = 8x8 pixel tile x 1 head.
// Epilogue writes bf16 hi/lo (direct input for the projection GEMM).
// ---------------------------------------------------------------------------
__global__ __launch_bounds__(256, 1)
void na_attn(const float* __restrict__ qkv,
             __nv_bfloat16* __restrict__ outh, __nv_bfloat16* __restrict__ outl)
{
    extern __shared__ float sm[];

    const int c0   = blockIdx.x * 8;
    const int r0   = blockIdx.y * 8;
    const int head = blockIdx.z;

    const int rlo = max(r0 - 3, 0);
    const int rhi = min(r0 + 10, HH - 1);
    const int nr  = rhi - rlo + 1;
    const int clo = max(c0 - 3, 0);
    const int chi = min(c0 + 10, WW - 1);
    const int nc  = chi - clo + 1;
    const int npx = nr * nc;

    float* sK = sm;
    float* sV = sm + npx * HD;

    const int tid = threadIdx.x;

    for (int t = tid; t < npx * (HD / 4); t += 256) {
        int p = t >> 3;
        int f = t & 7;
        int gy = rlo + p / nc;
        int gx = clo + p % nc;
        const float* base = qkv + (size_t)(gy * WW + gx) * C3 + head * HD;
        *(float4*)&sK[p * HD + f * 4] = *(const float4*)(base + CC + f * 4);
        *(float4*)&sV[p * HD + f * 4] = *(const float4*)(base + 2 * CC + f * 4);
    }
    __syncthreads();

    const int warp = tid >> 5;
    const int lane = tid & 31;
    const int sub  = lane >> 3;
    const int l8   = lane & 7;
    const int gy   = r0 + warp;
    const float scale = 0.17677669529663687f;   // 1/sqrt(32)

    const int sy = min(max(gy - 3, 0), HH - KK) - rlo;

#pragma unroll
    for (int t = 0; t < 2; t++) {
        const int gx = c0 + t * 4 + sub;
        const size_t pix = (size_t)(gy * WW + gx);

        float4 q4 = *(const float4*)&qkv[pix * C3 + head * HD + l8 * 4];
        q4.x *= scale; q4.y *= scale; q4.z *= scale; q4.w *= scale;

        const int sx = min(max(gx - 3, 0), WW - KK) - clo;
        const int base = (sy * nc + sx) * HD + l8 * 4;

        float sc[KK * KK];
#pragma unroll
        for (int p = 0; p < KK; p++) {
#pragma unroll
            for (int q = 0; q < KK; q++) {
                const float4 k4 = *(const float4*)&sK[base + (p * nc + q) * HD];
                float s = q4.x * k4.x;
                s = fmaf(q4.y, k4.y, s);
                s = fmaf(q4.z, k4.z, s);
                s = fmaf(q4.w, k4.w, s);
                s += __shfl_xor_sync(0xffffffffu, s, 4);
                s += __shfl_xor_sync(0xffffffffu, s, 2);
                s += __shfl_xor_sync(0xffffffffu, s, 1);
                sc[p * KK + q] = s;
            }
        }

        float m = sc[0];
#pragma unroll
        for (int i = 1; i < KK * KK; i++) m = fmaxf(m, sc[i]);

        float l = 0.0f;
        float4 acc = make_float4(0.f, 0.f, 0.f, 0.f);
#pragma unroll
        for (int p = 0; p < KK; p++) {
#pragma unroll
            for (int q = 0; q < KK; q++) {
                const float e = __expf(sc[p * KK + q] - m);
                l += e;
                const float4 v4 = *(const float4*)&sV[base + (p * nc + q) * HD];
                acc.x = fmaf(e, v4.x, acc.x);
                acc.y = fmaf(e, v4.y, acc.y);
                acc.z = fmaf(e, v4.z, acc.z);
                acc.w = fmaf(e, v4.w, acc.w);
            }
        }

        const float inv = 1.0f / l;
        float vals[4] = {acc.x * inv, acc.y * inv, acc.z * inv, acc.w * inv};
        const size_t idx = pix * CC + head * HD + l8 * 4;
#pragma unroll
        for (int j = 0; j < 4; j++) {
            __nv_bfloat16 hi = __float2bfloat16(vals[j]);
            outh[idx + j] = hi;
            outl[idx + j] = __float2bfloat16(vals[j] - __bfloat162float(hi));
        }
    }
}

// ---------------------------------------------------------------------------
// kernel_launch
// ---------------------------------------------------------------------------
extern "C" void kernel_launch(void* const* d_in, const int* in_sizes, int n_in,
                              void* d_out, int out_size)
{
    const float* x      = (const float*)d_in[0];
    const float* w_qkv  = (const float*)d_in[1];
    const float* b_qkv  = (const float*)d_in[2];
    const float* w_proj = (const float*)d_in[3];
    const float* b_proj = (const float*)d_in[4];
    float* out = (float*)d_out;

    float *qkv;
    __nv_bfloat16 *xh, *xl, *wqh, *wql, *wph, *wpl, *ath, *atl;
    cudaGetSymbolAddress((void**)&qkv, g_qkv);
    cudaGetSymbolAddress((void**)&xh,  g_xh);
    cudaGetSymbolAddress((void**)&xl,  g_xl);
    cudaGetSymbolAddress((void**)&wqh, g_wqkvT_h);
    cudaGetSymbolAddress((void**)&wql, g_wqkvT_l);
    cudaGetSymbolAddress((void**)&wph, g_wprojT_h);
    cudaGetSymbolAddress((void**)&wpl, g_wprojT_l);
    cudaGetSymbolAddress((void**)&ath, g_atth);
    cudaGetSymbolAddress((void**)&atl, g_attl);

    cudaFuncSetAttribute(gemm_mma, cudaFuncAttributeMaxDynamicSharedMemorySize,
                         GT_SMEM);
    cudaFuncSetAttribute(na_attn, cudaFuncAttributeMaxDynamicSharedMemorySize,
                         2 * 14 * 14 * HD * (int)sizeof(float));

    // 0) Prep: split x, transpose+split weights
    split_f32<<<(NPIX * CC + 255) / 256, 256>>>(x, xh, xl, NPIX * CC);
    transpose_split<<<(CC * C3 + 255) / 256, 256>>>(w_qkv, wqh, wql, CC, C3);
    transpose_split<<<(CC * CC + 255) / 256, 256>>>(w_proj, wph, wpl, CC, CC);

    // 1) QKV projection (tensor cores): [8192,256] @ [256,768] + b
    {
        dim3 grid(C3 / 128, NPIX / 128);
        gemm_mma<<<grid, 256, GT_SMEM>>>(xh, xl, wqh, wql, b_qkv, qkv, C3, CC);
    }

    // 2) Neighborhood attention (emits bf16 hi/lo)
    {
        const int smem = 2 * 14 * 14 * HD * (int)sizeof(float);  // 50176 B
        dim3 grid(WW / 8, HH / 8, NH);
        na_attn<<<grid, 256, smem>>>(qkv, ath, atl);
    }

    // 3) Output projection (tensor cores): [8192,256] @ [256,256] + b
    {
        dim3 grid(CC / 128, NPIX / 128);
        gemm_mma<<<grid, 256, GT_SMEM>>>(ath, atl, wph, wpl, b_proj, out, CC, CC);
    }
}

// round 6
// speedup vs baseline: 2.3796x; 1.1009x over previous
#include <cuda_runtime.h>
#include <cuda_bf16.h>
#include <cstdint>

// Problem constants
#define HH   64
#define WW   128
#define CC   256
#define NPIX (HH * WW)          // 8192
#define NH   8
#define HD   32
#define C3   (3 * CC)           // 768
#define KK   7

// ---------------------------------------------------------------------------
// Scratch (device globals; no allocation allowed)
// ---------------------------------------------------------------------------
__device__ __align__(16) float         g_qkv[NPIX * C3];       // 25 MB
__device__ __align__(16) __nv_bfloat16 g_xh[NPIX * CC];
__device__ __align__(16) __nv_bfloat16 g_xl[NPIX * CC];
__device__ __align__(16) __nv_bfloat16 g_wqkvT_h[C3 * CC];
__device__ __align__(16) __nv_bfloat16 g_wqkvT_l[C3 * CC];
__device__ __align__(16) __nv_bfloat16 g_wprojT_h[CC * CC];
__device__ __align__(16) __nv_bfloat16 g_wprojT_l[CC * CC];
__device__ __align__(16) __nv_bfloat16 g_atth[NPIX * CC];
__device__ __align__(16) __nv_bfloat16 g_attl[NPIX * CC];

// ---------------------------------------------------------------------------
// PTX helpers (baseline ISA: mma.sync / ldmatrix / cp.async)
// ---------------------------------------------------------------------------
__device__ __forceinline__ uint32_t smem_u32(const void* p) {
    uint32_t a;
    asm("{ .reg .u64 t; cvta.to.shared.u64 t, %1; cvt.u32.u64 %0, t; }"
        : "=r"(a) : "l"(p));
    return a;
}

__device__ __forceinline__ void cp_async16(uint32_t saddr, const void* gptr) {
    asm volatile("cp.async.cg.shared.global [%0], [%1], 16;"
                 :: "r"(saddr), "l"(gptr) : "memory");
}

__device__ __forceinline__ void ldsm_x4(uint32_t* r, uint32_t addr) {
    asm volatile("ldmatrix.sync.aligned.m8n8.x4.shared.b16 {%0,%1,%2,%3}, [%4];"
                 : "=r"(r[0]), "=r"(r[1]), "=r"(r[2]), "=r"(r[3]) : "r"(addr));
}

__device__ __forceinline__ void mma_16816(float* c, const uint32_t* a,
                                          const uint32_t* b) {
    asm volatile(
        "mma.sync.aligned.m16n8k16.row.col.f32.bf16.bf16.f32 "
        "{%0,%1,%2,%3}, {%4,%5,%6,%7}, {%8,%9}, {%0,%1,%2,%3};"
        : "+f"(c[0]), "+f"(c[1]), "+f"(c[2]), "+f"(c[3])
        : "r"(a[0]), "r"(a[1]), "r"(a[2]), "r"(a[3]), "r"(b[0]), "r"(b[1]));
}

// SW128 swizzle: chunk bits [4:6] ^= row bits [7:9] (conflict-free ldmatrix)
__device__ __forceinline__ uint32_t sw128(uint32_t off) {
    return off ^ ((off >> 3) & 0x70);
}

// ---------------------------------------------------------------------------
// Fused prep: split x (hi/lo bf16) + transpose/split both weight matrices
//   blocks [0, 8192)          : x       (NPIX*CC = 2M elems)
//   blocks [8192, 8960)       : w_qkv^T (CC x C3 -> C3 x CC, 768 blocks)
//   blocks [8960, 9216)       : w_proj^T (CC x CC, 256 blocks)
// ---------------------------------------------------------------------------
#define PREP_XB  (NPIX * CC / 256)            // 8192
#define PREP_QB  (CC * C3 / 256)              // 768
#define PREP_PB  (CC * CC / 256)              // 256

__global__ void prep_all(const float* __restrict__ x,
                         const float* __restrict__ wq,
                         const float* __restrict__ wp,
                         __nv_bfloat16* __restrict__ xh, __nv_bfloat16* __restrict__ xl,
                         __nv_bfloat16* __restrict__ qh, __nv_bfloat16* __restrict__ ql,
                         __nv_bfloat16* __restrict__ ph, __nv_bfloat16* __restrict__ pl)
{
    const int b = blockIdx.x;
    if (b < PREP_XB) {
        const int i = b * 256 + threadIdx.x;
        const float v = x[i];
        const __nv_bfloat16 hi = __float2bfloat16(v);
        xh[i] = hi;
        xl[i] = __float2bfloat16(v - __bfloat162float(hi));
    } else if (b < PREP_XB + PREP_QB) {
        const int i = (b - PREP_XB) * 256 + threadIdx.x;   // over C3*CC
        const int n = i / CC, k = i % CC;
        const float v = wq[(size_t)k * C3 + n];
        const __nv_bfloat16 hi = __float2bfloat16(v);
        qh[i] = hi;                                        // i == n*CC + k
        ql[i] = __float2bfloat16(v - __bfloat162float(hi));
    } else {
        const int i = (b - PREP_XB - PREP_QB) * 256 + threadIdx.x;  // CC*CC
        const int n = i / CC, k = i % CC;
        const float v = wp[(size_t)k * CC + n];
        const __nv_bfloat16 hi = __float2bfloat16(v);
        ph[i] = hi;
        pl[i] = __float2bfloat16(v - __bfloat162float(hi));
    }
}

// ---------------------------------------------------------------------------
// mma.sync bf16-split GEMM: C[M,N] = (Ah+Al)[M,K] @ (Bh+Bl)[N,K]^T + bias
// 3-term: Ah@Bh + Ah@Bl + Al@Bh. CTA tile 128x64, 8 warps (4M x 2N),
// warp tile 32x32. K chunks of 64, 2-stage cp.async pipeline.
// SW128-swizzled smem (exact 128B rows, no padding) -> 96KB, 2 CTAs/SM.
// ---------------------------------------------------------------------------
#define BKC 64
#define AB_BYTES (128 * 128)                 // 16384 per A buffer
#define BB_BYTES (64 * 128)                  // 8192  per B buffer
#define STG_BYTES (2 * AB_BYTES + 2 * BB_BYTES)  // 49152
#define GT_SMEM (2 * STG_BYTES)              // 98304

__global__ __launch_bounds__(256, 2)
void gemm_mma(const __nv_bfloat16* __restrict__ Ah, const __nv_bfloat16* __restrict__ Al,
              const __nv_bfloat16* __restrict__ Bh, const __nv_bfloat16* __restrict__ Bl,
              const float* __restrict__ bias, float* __restrict__ C, int N, int K)
{
    extern __shared__ char smem[];
    const uint32_t sb = smem_u32(smem);
    const int tid  = threadIdx.x;
    const int wid  = tid >> 5;
    const int lane = tid & 31;
    const int warpM = wid & 3;               // 0..3  (32 rows each)
    const int warpN = wid >> 2;              // 0..1  (32 cols each)

    const size_t aBase = (size_t)blockIdx.y * 128 * K;
    const size_t bBase = (size_t)blockIdx.x * 64 * K;
    const int nch = K / BKC;

    auto issue_chunk = [&](int c) {
        const uint32_t st = sb + (uint32_t)(c & 1) * STG_BYTES;
        const int k0 = c * BKC;
        // A hi/lo: 128 rows x 8 chunks = 1024 xfers each
#pragma unroll
        for (int i = 0; i < 4; i++) {
            const int idx = i * 256 + tid;
            const int r = idx >> 3, ch = idx & 7;
            const uint32_t so = sw128((uint32_t)r * 128 + (uint32_t)ch * 16);
            const size_t ga = aBase + (size_t)r * K + k0 + ch * 8;
            cp_async16(st + so, Ah + ga);
            cp_async16(st + AB_BYTES + so, Al + ga);
        }
        // B hi/lo: 64 rows x 8 chunks = 512 xfers each
#pragma unroll
        for (int i = 0; i < 2; i++) {
            const int idx = i * 256 + tid;
            const int r = idx >> 3, ch = idx & 7;
            const uint32_t so = sw128((uint32_t)r * 128 + (uint32_t)ch * 16);
            const size_t gb = bBase + (size_t)r * K + k0 + ch * 8;
            cp_async16(st + 2 * AB_BYTES + so, Bh + gb);
            cp_async16(st + 2 * AB_BYTES + BB_BYTES + so, Bl + gb);
        }
        asm volatile("cp.async.commit_group;" ::: "memory");
    };

    float acc[2][4][4];
#pragma unroll
    for (int i = 0; i < 2; i++)
#pragma unroll
        for (int j = 0; j < 4; j++)
#pragma unroll
            for (int t = 0; t < 4; t++) acc[i][j][t] = 0.0f;

    issue_chunk(0);

    for (int c = 0; c < nch; c++) {
        if (c + 1 < nch) {
            issue_chunk(c + 1);
            asm volatile("cp.async.wait_group 1;" ::: "memory");
        } else {
            asm volatile("cp.async.wait_group 0;" ::: "memory");
        }
        __syncthreads();

        const uint32_t st  = sb + (uint32_t)(c & 1) * STG_BYTES;
        const uint32_t sA0 = st;
        const uint32_t sA1 = st + AB_BYTES;
        const uint32_t sB0 = st + 2 * AB_BYTES;
        const uint32_t sB1 = st + 2 * AB_BYTES + BB_BYTES;

        const uint32_t arow  = (uint32_t)(warpM * 32 + (lane & 15));
        const uint32_t acolL = (uint32_t)((lane >> 4) * 16);
        const uint32_t brow  = (uint32_t)(warpN * 32 + (lane & 7) + ((lane >> 4) << 3));
        const uint32_t bcolL = (uint32_t)(((lane >> 3) & 1) * 16);

#pragma unroll
        for (int ks = 0; ks < 4; ks++) {
            const uint32_t kb = (uint32_t)ks * 32;

            uint32_t ah[2][4], al[2][4];
#pragma unroll
            for (int ma = 0; ma < 2; ma++) {
                const uint32_t off = sw128((arow + ma * 16) * 128 + kb + acolL);
                ldsm_x4(ah[ma], sA0 + off);
                ldsm_x4(al[ma], sA1 + off);
            }

            uint32_t bh[4][2], bl[4][2];
#pragma unroll
            for (int g = 0; g < 2; g++) {
                const uint32_t off = sw128((brow + g * 16) * 128 + kb + bcolL);
                uint32_t t0[4], t1[4];
                ldsm_x4(t0, sB0 + off);
                ldsm_x4(t1, sB1 + off);
                bh[2 * g][0] = t0[0]; bh[2 * g][1] = t0[1];
                bh[2 * g + 1][0] = t0[2]; bh[2 * g + 1][1] = t0[3];
                bl[2 * g][0] = t1[0]; bl[2 * g][1] = t1[1];
                bl[2 * g + 1][0] = t1[2]; bl[2 * g + 1][1] = t1[3];
            }

#pragma unroll
            for (int ma = 0; ma < 2; ma++)
#pragma unroll
                for (int na = 0; na < 4; na++) {
                    mma_16816(acc[ma][na], ah[ma], bh[na]);
                    mma_16816(acc[ma][na], ah[ma], bl[na]);
                    mma_16816(acc[ma][na], al[ma], bh[na]);
                }
        }
        __syncthreads();
    }

    // ---- epilogue: bias + store (float2 per fragment row) ----
    const int row0 = blockIdx.y * 128 + warpM * 32 + (lane >> 2);
    const int col0 = blockIdx.x * 64 + warpN * 32 + (lane & 3) * 2;
#pragma unroll
    for (int na = 0; na < 4; na++) {
        const int cc = col0 + na * 8;
        const float2 b2 = *(const float2*)&bias[cc];
#pragma unroll
        for (int ma = 0; ma < 2; ma++) {
            const int r = row0 + ma * 16;
            float2 o0, o1;
            o0.x = acc[ma][na][0] + b2.x;
            o0.y = acc[ma][na][1] + b2.y;
            o1.x = acc[ma][na][2] + b2.x;
            o1.y = acc[ma][na][3] + b2.y;
            *(float2*)&C[(size_t)r * N + cc]       = o0;
            *(float2*)&C[(size_t)(r + 8) * N + cc] = o1;
        }
    }
}

// ---------------------------------------------------------------------------
// 2D neighborhood attention (7x7), one block = 8x8 pixel tile x 1 head.
// Epilogue writes bf16 hi/lo (direct input for the projection GEMM).
// ---------------------------------------------------------------------------
__global__ __launch_bounds__(256, 1)
void na_attn(const float* __restrict__ qkv,
             __nv_bfloat16* __restrict__ outh, __nv_bfloat16* __restrict__ outl)
{
    extern __shared__ float sm[];

    const int c0   = blockIdx.x * 8;
    const int r0   = blockIdx.y * 8;
    const int head = blockIdx.z;

    const int rlo = max(r0 - 3, 0);
    const int rhi = min(r0 + 10, HH - 1);
    const int nr  = rhi - rlo + 1;
    const int clo = max(c0 - 3, 0);
    const int chi = min(c0 + 10, WW - 1);
    const int nc  = chi - clo + 1;
    const int npx = nr * nc;

    float* sK = sm;
    float* sV = sm + npx * HD;

    const int tid = threadIdx.x;

    for (int t = tid; t < npx * (HD / 4); t += 256) {
        int p = t >> 3;
        int f = t & 7;
        int gy = rlo + p / nc;
        int gx = clo + p % nc;
        const float* base = qkv + (size_t)(gy * WW + gx) * C3 + head * HD;
        *(float4*)&sK[p * HD + f * 4] = *(const float4*)(base + CC + f * 4);
        *(float4*)&sV[p * HD + f * 4] = *(const float4*)(base + 2 * CC + f * 4);
    }
    __syncthreads();

    const int warp = tid >> 5;
    const int lane = tid & 31;
    const int sub  = lane >> 3;
    const int l8   = lane & 7;
    const int gy   = r0 + warp;
    const float scale = 0.17677669529663687f;   // 1/sqrt(32)

    const int sy = min(max(gy - 3, 0), HH - KK) - rlo;

#pragma unroll
    for (int t = 0; t < 2; t++) {
        const int gx = c0 + t * 4 + sub;
        const size_t pix = (size_t)(gy * WW + gx);

        float4 q4 = *(const float4*)&qkv[pix * C3 + head * HD + l8 * 4];
        q4.x *= scale; q4.y *= scale; q4.z *= scale; q4.w *= scale;

        const int sx = min(max(gx - 3, 0), WW - KK) - clo;
        const int base = (sy * nc + sx) * HD + l8 * 4;

        float sc[KK * KK];
#pragma unroll
        for (int p = 0; p < KK; p++) {
#pragma unroll
            for (int q = 0; q < KK; q++) {
                const float4 k4 = *(const float4*)&sK[base + (p * nc + q) * HD];
                float s = q4.x * k4.x;
                s = fmaf(q4.y, k4.y, s);
                s = fmaf(q4.z, k4.z, s);
                s = fmaf(q4.w, k4.w, s);
                s += __shfl_xor_sync(0xffffffffu, s, 4);
                s += __shfl_xor_sync(0xffffffffu, s, 2);
                s += __shfl_xor_sync(0xffffffffu, s, 1);
                sc[p * KK + q] = s;
            }
        }

        float m = sc[0];
#pragma unroll
        for (int i = 1; i < KK * KK; i++) m = fmaxf(m, sc[i]);

        float l = 0.0f;
        float4 acc = make_float4(0.f, 0.f, 0.f, 0.f);
#pragma unroll
        for (int p = 0; p < KK; p++) {
#pragma unroll
            for (int q = 0; q < KK; q++) {
                const float e = __expf(sc[p * KK + q] - m);
                l += e;
                const float4 v4 = *(const float4*)&sV[base + (p * nc + q) * HD];
                acc.x = fmaf(e, v4.x, acc.x);
                acc.y = fmaf(e, v4.y, acc.y);
                acc.z = fmaf(e, v4.z, acc.z);
                acc.w = fmaf(e, v4.w, acc.w);
            }
        }

        const float inv = 1.0f / l;
        float vals[4] = {acc.x * inv, acc.y * inv, acc.z * inv, acc.w * inv};
        const size_t idx = pix * CC + head * HD + l8 * 4;
#pragma unroll
        for (int j = 0; j < 4; j++) {
            __nv_bfloat16 hi = __float2bfloat16(vals[j]);
            outh[idx + j] = hi;
            outl[idx + j] = __float2bfloat16(vals[j] - __bfloat162float(hi));
        }
    }
}

// ---------------------------------------------------------------------------
// kernel_launch
// ---------------------------------------------------------------------------
extern "C" void kernel_launch(void* const* d_in, const int* in_sizes, int n_in,
                              void* d_out, int out_size)
{
    const float* x      = (const float*)d_in[0];
    const float* w_qkv  = (const float*)d_in[1];
    const float* b_qkv  = (const float*)d_in[2];
    const float* w_proj = (const float*)d_in[3];
    const float* b_proj = (const float*)d_in[4];
    float* out = (float*)d_out;

    float *qkv;
    __nv_bfloat16 *xh, *xl, *wqh, *wql, *wph, *wpl, *ath, *atl;
    cudaGetSymbolAddress((void**)&qkv, g_qkv);
    cudaGetSymbolAddress((void**)&xh,  g_xh);
    cudaGetSymbolAddress((void**)&xl,  g_xl);
    cudaGetSymbolAddress((void**)&wqh, g_wqkvT_h);
    cudaGetSymbolAddress((void**)&wql, g_wqkvT_l);
    cudaGetSymbolAddress((void**)&wph, g_wprojT_h);
    cudaGetSymbolAddress((void**)&wpl, g_wprojT_l);
    cudaGetSymbolAddress((void**)&ath, g_atth);
    cudaGetSymbolAddress((void**)&atl, g_attl);

    cudaFuncSetAttribute(gemm_mma, cudaFuncAttributeMaxDynamicSharedMemorySize,
                         GT_SMEM);
    cudaFuncSetAttribute(na_attn, cudaFuncAttributeMaxDynamicSharedMemorySize,
                         2 * 14 * 14 * HD * (int)sizeof(float));

    // 0) Fused prep: split x + transpose/split both weights
    prep_all<<<PREP_XB + PREP_QB + PREP_PB, 256>>>(x, w_qkv, w_proj,
                                                   xh, xl, wqh, wql, wph, wpl);

    // 1) QKV projection (tensor cores): [8192,256] @ [256,768] + b
    {
        dim3 grid(C3 / 64, NPIX / 128);
        gemm_mma<<<grid, 256, GT_SMEM>>>(xh, xl, wqh, wql, b_qkv, qkv, C3, CC);
    }

    // 2) Neighborhood attention (emits bf16 hi/lo)
    {
        const int smem = 2 * 14 * 14 * HD * (int)sizeof(float);  // 50176 B
        dim3 grid(WW / 8, HH / 8, NH);
        na_attn<<<grid, 256, smem>>>(qkv, ath, atl);
    }

    // 3) Output projection (tensor cores): [8192,256] @ [256,256] + b
    {
        dim3 grid(CC / 64, NPIX / 128);
        gemm_mma<<<grid, 256, GT_SMEM>>>(ath, atl, wph, wpl, b_proj, out, CC, CC);
    }
}

// round 8
// speedup vs baseline: 2.5365x; 1.0660x over previous
#include <cuda_runtime.h>
#include <cuda_bf16.h>
#include <cuda_fp16.h>
#include <cstdint>

// Problem constants
#define HH   64
#define WW   128
#define CC   256
#define NPIX (HH * WW)          // 8192
#define NH   8
#define HD   32
#define C3   (3 * CC)           // 768
#define KK   7

// ---------------------------------------------------------------------------
// Scratch (device globals; no allocation allowed)
// ---------------------------------------------------------------------------
__device__ __align__(16) float         g_qkv[NPIX * C3];       // 25 MB
__device__ __align__(16) __nv_bfloat16 g_xh[NPIX * CC];
__device__ __align__(16) __nv_bfloat16 g_xl[NPIX * CC];
__device__ __align__(16) __nv_bfloat16 g_wqkvT_h[C3 * CC];
__device__ __align__(16) __nv_bfloat16 g_wqkvT_l[C3 * CC];
__device__ __align__(16) __nv_bfloat16 g_wprojT_h[CC * CC];
__device__ __align__(16) __nv_bfloat16 g_wprojT_l[CC * CC];
__device__ __align__(16) __nv_bfloat16 g_atth[NPIX * CC];
__device__ __align__(16) __nv_bfloat16 g_attl[NPIX * CC];

// 8-byte pair of half2 (4 fp16 values) for vectorized smem access
struct __align__(8) h2x2 { __half2 a, b; };

// ---------------------------------------------------------------------------
// PTX helpers (baseline ISA: mma.sync / ldmatrix / cp.async)
// ---------------------------------------------------------------------------
__device__ __forceinline__ uint32_t smem_u32(const void* p) {
    uint32_t a;
    asm("{ .reg .u64 t; cvta.to.shared.u64 t, %1; cvt.u32.u64 %0, t; }"
        : "=r"(a) : "l"(p));
    return a;
}

__device__ __forceinline__ void cp_async16(uint32_t saddr, const void* gptr) {
    asm volatile("cp.async.cg.shared.global [%0], [%1], 16;"
                 :: "r"(saddr), "l"(gptr) : "memory");
}

__device__ __forceinline__ void ldsm_x4(uint32_t* r, uint32_t addr) {
    asm volatile("ldmatrix.sync.aligned.m8n8.x4.shared.b16 {%0,%1,%2,%3}, [%4];"
                 : "=r"(r[0]), "=r"(r[1]), "=r"(r[2]), "=r"(r[3]) : "r"(addr));
}

__device__ __forceinline__ void mma_16816(float* c, const uint32_t* a,
                                          const uint32_t* b) {
    asm volatile(
        "mma.sync.aligned.m16n8k16.row.col.f32.bf16.bf16.f32 "
        "{%0,%1,%2,%3}, {%4,%5,%6,%7}, {%8,%9}, {%0,%1,%2,%3};"
        : "+f"(c[0]), "+f"(c[1]), "+f"(c[2]), "+f"(c[3])
        : "r"(a[0]), "r"(a[1]), "r"(a[2]), "r"(a[3]), "r"(b[0]), "r"(b[1]));
}

// SW128 swizzle: chunk bits [4:6] ^= row bits [7:9] (conflict-free ldmatrix)
__device__ __forceinline__ uint32_t sw128(uint32_t off) {
    return off ^ ((off >> 3) & 0x70);
}

// ---------------------------------------------------------------------------
// Fused prep: split x (hi/lo bf16) + transpose/split both weight matrices
// ---------------------------------------------------------------------------
#define PREP_XB  (NPIX * CC / 256)            // 8192
#define PREP_QB  (CC * C3 / 256)              // 768
#define PREP_PB  (CC * CC / 256)              // 256

__global__ void prep_all(const float* __restrict__ x,
                         const float* __restrict__ wq,
                         const float* __restrict__ wp,
                         __nv_bfloat16* __restrict__ xh, __nv_bfloat16* __restrict__ xl,
                         __nv_bfloat16* __restrict__ qh, __nv_bfloat16* __restrict__ ql,
                         __nv_bfloat16* __restrict__ ph, __nv_bfloat16* __restrict__ pl)
{
    const int b = blockIdx.x;
    if (b < PREP_XB) {
        const int i = b * 256 + threadIdx.x;
        const float v = x[i];
        const __nv_bfloat16 hi = __float2bfloat16(v);
        xh[i] = hi;
        xl[i] = __float2bfloat16(v - __bfloat162float(hi));
    } else if (b < PREP_XB + PREP_QB) {
        const int i = (b - PREP_XB) * 256 + threadIdx.x;   // over C3*CC
        const int n = i / CC, k = i % CC;
        const float v = wq[(size_t)k * C3 + n];
        const __nv_bfloat16 hi = __float2bfloat16(v);
        qh[i] = hi;                                        // i == n*CC + k
        ql[i] = __float2bfloat16(v - __bfloat162float(hi));
    } else {
        const int i = (b - PREP_XB - PREP_QB) * 256 + threadIdx.x;  // CC*CC
        const int n = i / CC, k = i % CC;
        const float v = wp[(size_t)k * CC + n];
        const __nv_bfloat16 hi = __float2bfloat16(v);
        ph[i] = hi;
        pl[i] = __float2bfloat16(v - __bfloat162float(hi));
    }
}

// ---------------------------------------------------------------------------
// mma.sync bf16-split GEMM: C[M,N] = (Ah+Al)[M,K] @ (Bh+Bl)[N,K]^T + bias
// 3-term: Ah@Bh + Ah@Bl + Al@Bh. CTA tile 128x64, 4 warps (2M x 2N),
// warp tile 64x32 (reuse 4 MMA/ldsm). K chunks of 64, 2-stage cp.async.
// SW128-swizzled smem, 96KB -> 2 CTAs/SM (8 warps/SM).
// ---------------------------------------------------------------------------
#define BKC 64
#define AB_BYTES (128 * 128)                 // 16384 per A buffer
#define BB_BYTES (64 * 128)                  // 8192  per B buffer
#define STG_BYTES (2 * AB_BYTES + 2 * BB_BYTES)  // 49152
#define GT_SMEM (2 * STG_BYTES)              // 98304

__global__ __launch_bounds__(128, 2)
void gemm_mma(const __nv_bfloat16* __restrict__ Ah, const __nv_bfloat16* __restrict__ Al,
              const __nv_bfloat16* __restrict__ Bh, const __nv_bfloat16* __restrict__ Bl,
              const float* __restrict__ bias, float* __restrict__ C, int N, int K)
{
    extern __shared__ char smem[];
    const uint32_t sb = smem_u32(smem);
    const int tid  = threadIdx.x;
    const int wid  = tid >> 5;
    const int lane = tid & 31;
    const int warpM = wid & 1;               // 0..1  (64 rows each)
    const int warpN = wid >> 1;              // 0..1  (32 cols each)

    const size_t aBase = (size_t)blockIdx.y * 128 * K;
    const size_t bBase = (size_t)blockIdx.x * 64 * K;
    const int nch = K / BKC;

    auto issue_chunk = [&](int c) {
        const uint32_t st = sb + (uint32_t)(c & 1) * STG_BYTES;
        const int k0 = c * BKC;
        // A hi/lo: 128 rows x 8 16B-chunks = 1024 xfers each
#pragma unroll
        for (int i = 0; i < 8; i++) {
            const int idx = i * 128 + tid;
            const int r = idx >> 3, ch = idx & 7;
            const uint32_t so = sw128((uint32_t)r * 128 + (uint32_t)ch * 16);
            const size_t ga = aBase + (size_t)r * K + k0 + ch * 8;
            cp_async16(st + so, Ah + ga);
            cp_async16(st + AB_BYTES + so, Al + ga);
        }
        // B hi/lo: 64 rows x 8 chunks = 512 xfers each
#pragma unroll
        for (int i = 0; i < 4; i++) {
            const int idx = i * 128 + tid;
            const int r = idx >> 3, ch = idx & 7;
            const uint32_t so = sw128((uint32_t)r * 128 + (uint32_t)ch * 16);
            const size_t gb = bBase + (size_t)r * K + k0 + ch * 8;
            cp_async16(st + 2 * AB_BYTES + so, Bh + gb);
            cp_async16(st + 2 * AB_BYTES + BB_BYTES + so, Bl + gb);
        }
        asm volatile("cp.async.commit_group;" ::: "memory");
    };

    float acc[4][4][4];
#pragma unroll
    for (int i = 0; i < 4; i++)
#pragma unroll
        for (int j = 0; j < 4; j++)
#pragma unroll
            for (int t = 0; t < 4; t++) acc[i][j][t] = 0.0f;

    issue_chunk(0);

    for (int c = 0; c < nch; c++) {
        if (c + 1 < nch) {
            issue_chunk(c + 1);
            asm volatile("cp.async.wait_group 1;" ::: "memory");
        } else {
            asm volatile("cp.async.wait_group 0;" ::: "memory");
        }
        __syncthreads();

        const uint32_t st  = sb + (uint32_t)(c & 1) * STG_BYTES;
        const uint32_t sA0 = st;
        const uint32_t sA1 = st + AB_BYTES;
        const uint32_t sB0 = st + 2 * AB_BYTES;
        const uint32_t sB1 = st + 2 * AB_BYTES + BB_BYTES;

        const uint32_t arow  = (uint32_t)(warpM * 64 + (lane & 15));
        const uint32_t acolL = (uint32_t)((lane >> 4) * 16);
        const uint32_t brow  = (uint32_t)(warpN * 32 + (lane & 7) + ((lane >> 4) << 3));
        const uint32_t bcolL = (uint32_t)(((lane >> 3) & 1) * 16);

#pragma unroll
        for (int ks = 0; ks < 4; ks++) {
            const uint32_t kb = (uint32_t)ks * 32;

            uint32_t ah[4][4], al[4][4];
#pragma unroll
            for (int ma = 0; ma < 4; ma++) {
                const uint32_t off = sw128((arow + ma * 16) * 128 + kb + acolL);
                ldsm_x4(ah[ma], sA0 + off);
                ldsm_x4(al[ma], sA1 + off);
            }

            uint32_t bh[4][2], bl[4][2];
#pragma unroll
            for (int g = 0; g < 2; g++) {
                const uint32_t off = sw128((brow + g * 16) * 128 + kb + bcolL);
                uint32_t t0[4], t1[4];
                ldsm_x4(t0, sB0 + off);
                ldsm_x4(t1, sB1 + off);
                bh[2 * g][0] = t0[0]; bh[2 * g][1] = t0[1];
                bh[2 * g + 1][0] = t0[2]; bh[2 * g + 1][1] = t0[3];
                bl[2 * g][0] = t1[0]; bl[2 * g][1] = t1[1];
                bl[2 * g + 1][0] = t1[2]; bl[2 * g + 1][1] = t1[3];
            }

#pragma unroll
            for (int ma = 0; ma < 4; ma++)
#pragma unroll
                for (int na = 0; na < 4; na++) {
                    mma_16816(acc[ma][na], ah[ma], bh[na]);
                    mma_16816(acc[ma][na], ah[ma], bl[na]);
                    mma_16816(acc[ma][na], al[ma], bh[na]);
                }
        }
        __syncthreads();
    }

    // ---- epilogue: bias + store (float2 per fragment row) ----
    const int row0 = blockIdx.y * 128 + warpM * 64 + (lane >> 2);
    const int col0 = blockIdx.x * 64 + warpN * 32 + (lane & 3) * 2;
#pragma unroll
    for (int na = 0; na < 4; na++) {
        const int cc = col0 + na * 8;
        const float2 b2 = *(const float2*)&bias[cc];
#pragma unroll
        for (int ma = 0; ma < 4; ma++) {
            const int r = row0 + ma * 16;
            float2 o0, o1;
            o0.x = acc[ma][na][0] + b2.x;
            o0.y = acc[ma][na][1] + b2.y;
            o1.x = acc[ma][na][2] + b2.x;
            o1.y = acc[ma][na][3] + b2.y;
            *(float2*)&C[(size_t)r * N + cc]       = o0;
            *(float2*)&C[(size_t)(r + 8) * N + cc] = o1;
        }
    }
}

// ---------------------------------------------------------------------------
// 2D neighborhood attention (7x7), one block = 8x8 pixel tile x 1 head.
// K/V staged in smem as fp16 half2 pairs (halves crossbar traffic; |vals|
// small so fp16 rounding ~1e-4 rel). q stays fp32.
// 8 lanes per pixel, lane owns 4 dims (one LDS.64 per neighbor per pass).
// ---------------------------------------------------------------------------
__global__ __launch_bounds__(256, 1)
void na_attn(const float* __restrict__ qkv,
             __nv_bfloat16* __restrict__ outh, __nv_bfloat16* __restrict__ outl)
{
    extern __shared__ h2x2 smn[];

    const int c0   = blockIdx.x * 8;
    const int r0   = blockIdx.y * 8;
    const int head = blockIdx.z;

    const int rlo = max(r0 - 3, 0);
    const int rhi = min(r0 + 10, HH - 1);
    const int nr  = rhi - rlo + 1;
    const int clo = max(c0 - 3, 0);
    const int chi = min(c0 + 10, WW - 1);
    const int nc  = chi - clo + 1;
    const int npx = nr * nc;

    h2x2* sK = smn;                    // npx * 8 h2x2 (32 halves per pixel)
    h2x2* sV = smn + npx * 8;

    const int tid = threadIdx.x;

    // Load K/V window, converting fp32 -> fp16 (one h2x2 = 4 dims)
    for (int t = tid; t < npx * (HD / 4); t += 256) {
        int p = t >> 3;
        int f = t & 7;
        int gy = rlo + p / nc;
        int gx = clo + p % nc;
        const float* base = qkv + (size_t)(gy * WW + gx) * C3 + head * HD;
        float4 kv = *(const float4*)(base + CC + f * 4);
        float4 vv = *(const float4*)(base + 2 * CC + f * 4);
        h2x2 kp, vp;
        kp.a = __floats2half2_rn(kv.x, kv.y);
        kp.b = __floats2half2_rn(kv.z, kv.w);
        vp.a = __floats2half2_rn(vv.x, vv.y);
        vp.b = __floats2half2_rn(vv.z, vv.w);
        sK[p * 8 + f] = kp;
        sV[p * 8 + f] = vp;
    }
    __syncthreads();

    const int warp = tid >> 5;
    const int lane = tid & 31;
    const int sub  = lane >> 3;
    const int l8   = lane & 7;
    const int gy   = r0 + warp;
    const float scale = 0.17677669529663687f;   // 1/sqrt(32)

    const int sy = min(max(gy - 3, 0), HH - KK) - rlo;

#pragma unroll
    for (int t = 0; t < 2; t++) {
        const int gx = c0 + t * 4 + sub;
        const size_t pix = (size_t)(gy * WW + gx);

        float4 q4 = *(const float4*)&qkv[pix * C3 + head * HD + l8 * 4];
        q4.x *= scale; q4.y *= scale; q4.z *= scale; q4.w *= scale;

        const int sx = min(max(gx - 3, 0), WW - KK) - clo;
        const int base = (sy * nc + sx) * 8 + l8;   // h2x2 index

        float sc[KK * KK];
#pragma unroll
        for (int p = 0; p < KK; p++) {
#pragma unroll
            for (int q = 0; q < KK; q++) {
                const h2x2 kp = sK[base + (p * nc + q) * 8];
                const float2 k01 = __half22float2(kp.a);
                const float2 k23 = __half22float2(kp.b);
                float s = q4.x * k01.x;
                s = fmaf(q4.y, k01.y, s);
                s = fmaf(q4.z, k23.x, s);
                s = fmaf(q4.w, k23.y, s);
                s += __shfl_xor_sync(0xffffffffu, s, 4);
                s += __shfl_xor_sync(0xffffffffu, s, 2);
                s += __shfl_xor_sync(0xffffffffu, s, 1);
                sc[p * KK + q] = s;
            }
        }

        float m = sc[0];
#pragma unroll
        for (int i = 1; i < KK * KK; i++) m = fmaxf(m, sc[i]);

        float l = 0.0f;
        float4 acc = make_float4(0.f, 0.f, 0.f, 0.f);
#pragma unroll
        for (int p = 0; p < KK; p++) {
#pragma unroll
            for (int q = 0; q < KK; q++) {
                const float e = __expf(sc[p * KK + q] - m);
                l += e;
                const h2x2 vp = sV[base + (p * nc + q) * 8];
                const float2 v01 = __half22float2(vp.a);
                const float2 v23 = __half22float2(vp.b);
                acc.x = fmaf(e, v01.x, acc.x);
                acc.y = fmaf(e, v01.y, acc.y);
                acc.z = fmaf(e, v23.x, acc.z);
                acc.w = fmaf(e, v23.y, acc.w);
            }
        }

        const float inv = 1.0f / l;
        float vals[4] = {acc.x * inv, acc.y * inv, acc.z * inv, acc.w * inv};
        const size_t idx = pix * CC + head * HD + l8 * 4;
#pragma unroll
        for (int j = 0; j < 4; j++) {
            __nv_bfloat16 hi = __float2bfloat16(vals[j]);
            outh[idx + j] = hi;
            outl[idx + j] = __float2bfloat16(vals[j] - __bfloat162float(hi));
        }
    }
}

// ---------------------------------------------------------------------------
// kernel_launch
// ---------------------------------------------------------------------------
extern "C" void kernel_launch(void* const* d_in, const int* in_sizes, int n_in,
                              void* d_out, int out_size)
{
    const float* x      = (const float*)d_in[0];
    const float* w_qkv  = (const float*)d_in[1];
    const float* b_qkv  = (const float*)d_in[2];
    const float* w_proj = (const float*)d_in[3];
    const float* b_proj = (const float*)d_in[4];
    float* out = (float*)d_out;

    float *qkv;
    __nv_bfloat16 *xh, *xl, *wqh, *wql, *wph, *wpl, *ath, *atl;
    cudaGetSymbolAddress((void**)&qkv, g_qkv);
    cudaGetSymbolAddress((void**)&xh,  g_xh);
    cudaGetSymbolAddress((void**)&xl,  g_xl);
    cudaGetSymbolAddress((void**)&wqh, g_wqkvT_h);
    cudaGetSymbolAddress((void**)&wql, g_wqkvT_l);
    cudaGetSymbolAddress((void**)&wph, g_wprojT_h);
    cudaGetSymbolAddress((void**)&wpl, g_wprojT_l);
    cudaGetSymbolAddress((void**)&ath, g_atth);
    cudaGetSymbolAddress((void**)&atl, g_attl);

    cudaFuncSetAttribute(gemm_mma, cudaFuncAttributeMaxDynamicSharedMemorySize,
                         GT_SMEM);

    // 0) Fused prep: split x + transpose/split both weights
    prep_all<<<PREP_XB + PREP_QB + PREP_PB, 256>>>(x, w_qkv, w_proj,
                                                   xh, xl, wqh, wql, wph, wpl);

    // 1) QKV projection (tensor cores): [8192,256] @ [256,768] + b
    {
        dim3 grid(C3 / 64, NPIX / 128);
        gemm_mma<<<grid, 128, GT_SMEM>>>(xh, xl, wqh, wql, b_qkv, qkv, C3, CC);
    }

    // 2) Neighborhood attention (fp16 K/V smem; emits bf16 hi/lo)
    {
        const int smem = 2 * 14 * 14 * 8 * (int)sizeof(h2x2);  // 25088 B
        dim3 grid(WW / 8, HH / 8, NH);
        na_attn<<<grid, 256, smem>>>(qkv, ath, atl);
    }

    // 3) Output projection (tensor cores): [8192,256] @ [256,256] + b
    {
        dim3 grid(CC / 64, NPIX / 128);
        gemm_mma<<<grid, 128, GT_SMEM>>>(ath, atl, wph, wpl, b_proj, out, CC, CC);
    }
}

// round 9
// speedup vs baseline: 2.7991x; 1.1035x over previous
#include <cuda_runtime.h>
#include <cuda_bf16.h>
#include <cuda_fp16.h>
#include <cstdint>

// Problem constants
#define HH   64
#define WW   128
#define CC   256
#define NPIX (HH * WW)          // 8192
#define NH   8
#define HD   32
#define C3   (3 * CC)           // 768
#define KK   7

// ---------------------------------------------------------------------------
// Scratch (device globals; no allocation allowed)
// ---------------------------------------------------------------------------
__device__ __align__(16) float         g_qkv[NPIX * C3];       // 25 MB
__device__ __align__(16) __nv_bfloat16 g_xh[NPIX * CC];
__device__ __align__(16) __nv_bfloat16 g_xl[NPIX * CC];
__device__ __align__(16) __nv_bfloat16 g_wqkvT_h[C3 * CC];
__device__ __align__(16) __nv_bfloat16 g_wqkvT_l[C3 * CC];
__device__ __align__(16) __nv_bfloat16 g_wprojT_h[CC * CC];
__device__ __align__(16) __nv_bfloat16 g_wprojT_l[CC * CC];
__device__ __align__(16) __nv_bfloat16 g_atth[NPIX * CC];
__device__ __align__(16) __nv_bfloat16 g_attl[NPIX * CC];

// 8-byte pair of half2 (4 fp16 values) for vectorized smem access
struct __align__(8) h2x2 { __half2 a, b; };

// ---------------------------------------------------------------------------
// PTX helpers (baseline ISA: mma.sync / ldmatrix / cp.async)
// ---------------------------------------------------------------------------
__device__ __forceinline__ uint32_t smem_u32(const void* p) {
    uint32_t a;
    asm("{ .reg .u64 t; cvta.to.shared.u64 t, %1; cvt.u32.u64 %0, t; }"
        : "=r"(a) : "l"(p));
    return a;
}

__device__ __forceinline__ void cp_async16(uint32_t saddr, const void* gptr) {
    asm volatile("cp.async.cg.shared.global [%0], [%1], 16;"
                 :: "r"(saddr), "l"(gptr) : "memory");
}

__device__ __forceinline__ void ldsm_x4(uint32_t* r, uint32_t addr) {
    asm volatile("ldmatrix.sync.aligned.m8n8.x4.shared.b16 {%0,%1,%2,%3}, [%4];"
                 : "=r"(r[0]), "=r"(r[1]), "=r"(r[2]), "=r"(r[3]) : "r"(addr));
}

__device__ __forceinline__ void mma_16816(float* c, const uint32_t* a,
                                          const uint32_t* b) {
    asm volatile(
        "mma.sync.aligned.m16n8k16.row.col.f32.bf16.bf16.f32 "
        "{%0,%1,%2,%3}, {%4,%5,%6,%7}, {%8,%9}, {%0,%1,%2,%3};"
        : "+f"(c[0]), "+f"(c[1]), "+f"(c[2]), "+f"(c[3])
        : "r"(a[0]), "r"(a[1]), "r"(a[2]), "r"(a[3]), "r"(b[0]), "r"(b[1]));
}

// SW128 swizzle: chunk bits [4:6] ^= row bits [7:9] (conflict-free ldmatrix)
__device__ __forceinline__ uint32_t sw128(uint32_t off) {
    return off ^ ((off >> 3) & 0x70);
}

// ---------------------------------------------------------------------------
// Fused prep: split x (hi/lo bf16) + transpose/split both weight matrices
// ---------------------------------------------------------------------------
#define PREP_XB  (NPIX * CC / 256)            // 8192
#define PREP_QB  (CC * C3 / 256)              // 768
#define PREP_PB  (CC * CC / 256)              // 256

__global__ void prep_all(const float* __restrict__ x,
                         const float* __restrict__ wq,
                         const float* __restrict__ wp,
                         __nv_bfloat16* __restrict__ xh, __nv_bfloat16* __restrict__ xl,
                         __nv_bfloat16* __restrict__ qh, __nv_bfloat16* __restrict__ ql,
                         __nv_bfloat16* __restrict__ ph, __nv_bfloat16* __restrict__ pl)
{
    const int b = blockIdx.x;
    if (b < PREP_XB) {
        const int i = b * 256 + threadIdx.x;
        const float v = x[i];
        const __nv_bfloat16 hi = __float2bfloat16(v);
        xh[i] = hi;
        xl[i] = __float2bfloat16(v - __bfloat162float(hi));
    } else if (b < PREP_XB + PREP_QB) {
        const int i = (b - PREP_XB) * 256 + threadIdx.x;   // over C3*CC
        const int n = i / CC, k = i % CC;
        const float v = wq[(size_t)k * C3 + n];
        const __nv_bfloat16 hi = __float2bfloat16(v);
        qh[i] = hi;                                        // i == n*CC + k
        ql[i] = __float2bfloat16(v - __bfloat162float(hi));
    } else {
        const int i = (b - PREP_XB - PREP_QB) * 256 + threadIdx.x;  // CC*CC
        const int n = i / CC, k = i % CC;
        const float v = wp[(size_t)k * CC + n];
        const __nv_bfloat16 hi = __float2bfloat16(v);
        ph[i] = hi;
        pl[i] = __float2bfloat16(v - __bfloat162float(hi));
    }
}

// ---------------------------------------------------------------------------
// mma.sync bf16-split GEMM: C[M,N] = (Ah+Al)[M,K] @ (Bh+Bl)[N,K]^T + bias
// 3-term: Ah@Bh + Ah@Bl + Al@Bh. CTA tile 128x64, 4 warps (2M x 2N),
// warp tile 64x32. K chunks of 64, 2-stage cp.async pipeline.
// Fragment double-buffering across ks hides ldmatrix latency.
// ---------------------------------------------------------------------------
#define BKC 64
#define AB_BYTES (128 * 128)                 // 16384 per A buffer
#define BB_BYTES (64 * 128)                  // 8192  per B buffer
#define STG_BYTES (2 * AB_BYTES + 2 * BB_BYTES)  // 49152
#define GT_SMEM (2 * STG_BYTES)              // 98304

__global__ __launch_bounds__(128, 2)
void gemm_mma(const __nv_bfloat16* __restrict__ Ah, const __nv_bfloat16* __restrict__ Al,
              const __nv_bfloat16* __restrict__ Bh, const __nv_bfloat16* __restrict__ Bl,
              const float* __restrict__ bias, float* __restrict__ C, int N, int K)
{
    extern __shared__ char smem[];
    const uint32_t sb = smem_u32(smem);
    const int tid  = threadIdx.x;
    const int wid  = tid >> 5;
    const int lane = tid & 31;
    const int warpM = wid & 1;               // 0..1  (64 rows each)
    const int warpN = wid >> 1;              // 0..1  (32 cols each)

    const size_t aBase = (size_t)blockIdx.y * 128 * K;
    const size_t bBase = (size_t)blockIdx.x * 64 * K;
    const int nch = K / BKC;

    auto issue_chunk = [&](int c) {
        const uint32_t st = sb + (uint32_t)(c & 1) * STG_BYTES;
        const int k0 = c * BKC;
#pragma unroll
        for (int i = 0; i < 8; i++) {
            const int idx = i * 128 + tid;
            const int r = idx >> 3, ch = idx & 7;
            const uint32_t so = sw128((uint32_t)r * 128 + (uint32_t)ch * 16);
            const size_t ga = aBase + (size_t)r * K + k0 + ch * 8;
            cp_async16(st + so, Ah + ga);
            cp_async16(st + AB_BYTES + so, Al + ga);
        }
#pragma unroll
        for (int i = 0; i < 4; i++) {
            const int idx = i * 128 + tid;
            const int r = idx >> 3, ch = idx & 7;
            const uint32_t so = sw128((uint32_t)r * 128 + (uint32_t)ch * 16);
            const size_t gb = bBase + (size_t)r * K + k0 + ch * 8;
            cp_async16(st + 2 * AB_BYTES + so, Bh + gb);
            cp_async16(st + 2 * AB_BYTES + BB_BYTES + so, Bl + gb);
        }
        asm volatile("cp.async.commit_group;" ::: "memory");
    };

    float acc[4][4][4];
#pragma unroll
    for (int i = 0; i < 4; i++)
#pragma unroll
        for (int j = 0; j < 4; j++)
#pragma unroll
            for (int t = 0; t < 4; t++) acc[i][j][t] = 0.0f;

    // ldmatrix lane address components
    const uint32_t arow  = (uint32_t)(warpM * 64 + (lane & 15));
    const uint32_t acolL = (uint32_t)((lane >> 4) * 16);
    const uint32_t brow  = (uint32_t)(warpN * 32 + (lane & 7) + ((lane >> 4) << 3));
    const uint32_t bcolL = (uint32_t)(((lane >> 3) & 1) * 16);

    // double-buffered fragments
    uint32_t ah[2][4][4], al[2][4][4], bh[2][4][2], bl[2][4][2];

    auto load_frags = [&](uint32_t sA0, uint32_t sA1, uint32_t sB0, uint32_t sB1,
                          int ks, int buf) {
        const uint32_t kb = (uint32_t)ks * 32;
#pragma unroll
        for (int ma = 0; ma < 4; ma++) {
            const uint32_t off = sw128((arow + ma * 16) * 128 + kb + acolL);
            ldsm_x4(ah[buf][ma], sA0 + off);
            ldsm_x4(al[buf][ma], sA1 + off);
        }
#pragma unroll
        for (int g = 0; g < 2; g++) {
            const uint32_t off = sw128((brow + g * 16) * 128 + kb + bcolL);
            uint32_t t0[4], t1[4];
            ldsm_x4(t0, sB0 + off);
            ldsm_x4(t1, sB1 + off);
            bh[buf][2 * g][0] = t0[0]; bh[buf][2 * g][1] = t0[1];
            bh[buf][2 * g + 1][0] = t0[2]; bh[buf][2 * g + 1][1] = t0[3];
            bl[buf][2 * g][0] = t1[0]; bl[buf][2 * g][1] = t1[1];
            bl[buf][2 * g + 1][0] = t1[2]; bl[buf][2 * g + 1][1] = t1[3];
        }
    };

    issue_chunk(0);

    for (int c = 0; c < nch; c++) {
        if (c + 1 < nch) {
            issue_chunk(c + 1);
            asm volatile("cp.async.wait_group 1;" ::: "memory");
        } else {
            asm volatile("cp.async.wait_group 0;" ::: "memory");
        }
        __syncthreads();

        const uint32_t st  = sb + (uint32_t)(c & 1) * STG_BYTES;
        const uint32_t sA0 = st;
        const uint32_t sA1 = st + AB_BYTES;
        const uint32_t sB0 = st + 2 * AB_BYTES;
        const uint32_t sB1 = st + 2 * AB_BYTES + BB_BYTES;

        load_frags(sA0, sA1, sB0, sB1, 0, 0);

#pragma unroll
        for (int ks = 0; ks < 4; ks++) {
            const int cur = ks & 1;
            if (ks + 1 < 4) load_frags(sA0, sA1, sB0, sB1, ks + 1, cur ^ 1);
#pragma unroll
            for (int ma = 0; ma < 4; ma++)
#pragma unroll
                for (int na = 0; na < 4; na++) {
                    mma_16816(acc[ma][na], ah[cur][ma], bh[cur][na]);
                    mma_16816(acc[ma][na], ah[cur][ma], bl[cur][na]);
                    mma_16816(acc[ma][na], al[cur][ma], bh[cur][na]);
                }
        }
        __syncthreads();
    }

    // ---- epilogue: bias + store (float2 per fragment row) ----
    const int row0 = blockIdx.y * 128 + warpM * 64 + (lane >> 2);
    const int col0 = blockIdx.x * 64 + warpN * 32 + (lane & 3) * 2;
#pragma unroll
    for (int na = 0; na < 4; na++) {
        const int cc = col0 + na * 8;
        const float2 b2 = *(const float2*)&bias[cc];
#pragma unroll
        for (int ma = 0; ma < 4; ma++) {
            const int r = row0 + ma * 16;
            float2 o0, o1;
            o0.x = acc[ma][na][0] + b2.x;
            o0.y = acc[ma][na][1] + b2.y;
            o1.x = acc[ma][na][2] + b2.x;
            o1.y = acc[ma][na][3] + b2.y;
            *(float2*)&C[(size_t)r * N + cc]       = o0;
            *(float2*)&C[(size_t)(r + 8) * N + cc] = o1;
        }
    }
}

// ---------------------------------------------------------------------------
// 2D neighborhood attention (7x7), one block = 8x8 pixel tile x 1 head.
// fp16 K/V smem. 8 lanes per pixel (lane owns 4 dims).
// Pass 1 uses an 8x8 transpose-reduce (7 shfl per 8 neighbors) so each lane
// OWNS 6 full scores; exp computed once per neighbor (8 MUFU/round vs 49);
// pass 2 rebroadcasts e with one width-8 shfl per neighbor.
// ---------------------------------------------------------------------------
__global__ __launch_bounds__(256, 1)
void na_attn(const float* __restrict__ qkv,
             __nv_bfloat16* __restrict__ outh, __nv_bfloat16* __restrict__ outl)
{
    extern __shared__ h2x2 smn[];

    const int c0   = blockIdx.x * 8;
    const int r0   = blockIdx.y * 8;
    const int head = blockIdx.z;

    const int rlo = max(r0 - 3, 0);
    const int rhi = min(r0 + 10, HH - 1);
    const int nr  = rhi - rlo + 1;
    const int clo = max(c0 - 3, 0);
    const int chi = min(c0 + 10, WW - 1);
    const int nc  = chi - clo + 1;
    const int npx = nr * nc;

    h2x2* sK = smn;                    // npx * 8 h2x2 (32 halves per pixel)
    h2x2* sV = smn + npx * 8;

    const int tid = threadIdx.x;

    // Load K/V window, converting fp32 -> fp16 (one h2x2 = 4 dims)
    for (int t = tid; t < npx * (HD / 4); t += 256) {
        int p = t >> 3;
        int f = t & 7;
        int gy = rlo + p / nc;
        int gx = clo + p % nc;
        const float* base = qkv + (size_t)(gy * WW + gx) * C3 + head * HD;
        float4 kv = *(const float4*)(base + CC + f * 4);
        float4 vv = *(const float4*)(base + 2 * CC + f * 4);
        h2x2 kp, vp;
        kp.a = __floats2half2_rn(kv.x, kv.y);
        kp.b = __floats2half2_rn(kv.z, kv.w);
        vp.a = __floats2half2_rn(vv.x, vv.y);
        vp.b = __floats2half2_rn(vv.z, vv.w);
        sK[p * 8 + f] = kp;
        sV[p * 8 + f] = vp;
    }
    __syncthreads();

    const int warp = tid >> 5;
    const int lane = tid & 31;
    const int sub  = lane >> 3;
    const int l8   = lane & 7;
    const int gy   = r0 + warp;
    const float scale = 0.17677669529663687f;   // 1/sqrt(32)

    const int sy = min(max(gy - 3, 0), HH - KK) - rlo;

#pragma unroll
    for (int t = 0; t < 2; t++) {
        const int gx = c0 + t * 4 + sub;
        const size_t pix = (size_t)(gy * WW + gx);

        float4 q4 = *(const float4*)&qkv[pix * C3 + head * HD + l8 * 4];
        q4.x *= scale; q4.y *= scale; q4.z *= scale; q4.w *= scale;

        const int sx = min(max(gx - 3, 0), WW - KK) - clo;
        const int base = (sy * nc + sx) * 8 + l8;   // h2x2 index

        // ---- pass 1: scores. 6 groups of 8 + neighbor 48 ----
        float own[6];      // lane owns score of neighbor g*8 + l8
#pragma unroll
        for (int g = 0; g < 6; g++) {
            float r[8];
#pragma unroll
            for (int j = 0; j < 8; j++) {
                const int idx = g * 8 + j;
                const int p = idx / KK, q = idx % KK;
                const h2x2 kp = sK[base + (p * nc + q) * 8];
                const float2 k01 = __half22float2(kp.a);
                const float2 k23 = __half22float2(kp.b);
                float s = q4.x * k01.x;
                s = fmaf(q4.y, k01.y, s);
                s = fmaf(q4.z, k23.x, s);
                s = fmaf(q4.w, k23.y, s);
                r[j] = s;
            }
            // 8x8 transpose-reduce: 7 shfl; lane l8 ends with neighbor g*8+l8
#pragma unroll
            for (int j = 0; j < 4; j++) {
                float snd = (l8 & 4) ? r[j] : r[j + 4];
                float rcv = __shfl_xor_sync(0xffffffffu, snd, 4);
                r[j] = ((l8 & 4) ? r[j + 4] : r[j]) + rcv;
            }
#pragma unroll
            for (int j = 0; j < 2; j++) {
                float snd = (l8 & 2) ? r[j] : r[j + 2];
                float rcv = __shfl_xor_sync(0xffffffffu, snd, 2);
                r[j] = ((l8 & 2) ? r[j + 2] : r[j]) + rcv;
            }
            {
                float snd = (l8 & 1) ? r[0] : r[1];
                float rcv = __shfl_xor_sync(0xffffffffu, snd, 1);
                r[0] = ((l8 & 1) ? r[1] : r[0]) + rcv;
            }
            own[g] = r[0];
        }
        // neighbor 48 (p=6,q=6): classic butterfly, all lanes get it
        float s48;
        {
            const h2x2 kp = sK[base + (6 * nc + 6) * 8];
            const float2 k01 = __half22float2(kp.a);
            const float2 k23 = __half22float2(kp.b);
            float s = q4.x * k01.x;
            s = fmaf(q4.y, k01.y, s);
            s = fmaf(q4.z, k23.x, s);
            s = fmaf(q4.w, k23.y, s);
            s += __shfl_xor_sync(0xffffffffu, s, 4);
            s += __shfl_xor_sync(0xffffffffu, s, 2);
            s += __shfl_xor_sync(0xffffffffu, s, 1);
            s48 = s;
        }

        // ---- max (distributed + butterfly) ----
        float m = s48;
#pragma unroll
        for (int g = 0; g < 6; g++) m = fmaxf(m, own[g]);
        m = fmaxf(m, __shfl_xor_sync(0xffffffffu, m, 4));
        m = fmaxf(m, __shfl_xor_sync(0xffffffffu, m, 2));
        m = fmaxf(m, __shfl_xor_sync(0xffffffffu, m, 1));

        // ---- exp (once per neighbor) + sum ----
        float e[6];
        float esum = 0.0f;
#pragma unroll
        for (int g = 0; g < 6; g++) {
            e[g] = __expf(own[g] - m);
            esum += e[g];
        }
        esum += __shfl_xor_sync(0xffffffffu, esum, 4);
        esum += __shfl_xor_sync(0xffffffffu, esum, 2);
        esum += __shfl_xor_sync(0xffffffffu, esum, 1);
        const float e48 = __expf(s48 - m);
        const float l = esum + e48;

        // ---- pass 2: weighted V accumulation ----
        float4 acc = make_float4(0.f, 0.f, 0.f, 0.f);
#pragma unroll
        for (int g = 0; g < 6; g++) {
#pragma unroll
            for (int j = 0; j < 8; j++) {
                const float eb = __shfl_sync(0xffffffffu, e[g], j, 8);
                const int idx = g * 8 + j;
                const int p = idx / KK, q = idx % KK;
                const h2x2 vp = sV[base + (p * nc + q) * 8];
                const float2 v01 = __half22float2(vp.a);
                const float2 v23 = __half22float2(vp.b);
                acc.x = fmaf(eb, v01.x, acc.x);
                acc.y = fmaf(eb, v01.y, acc.y);
                acc.z = fmaf(eb, v23.x, acc.z);
                acc.w = fmaf(eb, v23.y, acc.w);
            }
        }
        {
            const h2x2 vp = sV[base + (6 * nc + 6) * 8];
            const float2 v01 = __half22float2(vp.a);
            const float2 v23 = __half22float2(vp.b);
            acc.x = fmaf(e48, v01.x, acc.x);
            acc.y = fmaf(e48, v01.y, acc.y);
            acc.z = fmaf(e48, v23.x, acc.z);
            acc.w = fmaf(e48, v23.y, acc.w);
        }

        const float inv = 1.0f / l;
        float vals[4] = {acc.x * inv, acc.y * inv, acc.z * inv, acc.w * inv};
        const size_t idx = pix * CC + head * HD + l8 * 4;
#pragma unroll
        for (int j = 0; j < 4; j++) {
            __nv_bfloat16 hi = __float2bfloat16(vals[j]);
            outh[idx + j] = hi;
            outl[idx + j] = __float2bfloat16(vals[j] - __bfloat162float(hi));
        }
    }
}

// ---------------------------------------------------------------------------
// kernel_launch
// ---------------------------------------------------------------------------
extern "C" void kernel_launch(void* const* d_in, const int* in_sizes, int n_in,
                              void* d_out, int out_size)
{
    const float* x      = (const float*)d_in[0];
    const float* w_qkv  = (const float*)d_in[1];
    const float* b_qkv  = (const float*)d_in[2];
    const float* w_proj = (const float*)d_in[3];
    const float* b_proj = (const float*)d_in[4];
    float* out = (float*)d_out;

    float *qkv;
    __nv_bfloat16 *xh, *xl, *wqh, *wql, *wph, *wpl, *ath, *atl;
    cudaGetSymbolAddress((void**)&qkv, g_qkv);
    cudaGetSymbolAddress((void**)&xh,  g_xh);
    cudaGetSymbolAddress((void**)&xl,  g_xl);
    cudaGetSymbolAddress((void**)&wqh, g_wqkvT_h);
    cudaGetSymbolAddress((void**)&wql, g_wqkvT_l);
    cudaGetSymbolAddress((void**)&wph, g_wprojT_h);
    cudaGetSymbolAddress((void**)&wpl, g_wprojT_l);
    cudaGetSymbolAddress((void**)&ath, g_atth);
    cudaGetSymbolAddress((void**)&atl, g_attl);

    cudaFuncSetAttribute(gemm_mma, cudaFuncAttributeMaxDynamicSharedMemorySize,
                         GT_SMEM);

    // 0) Fused prep: split x + transpose/split both weights
    prep_all<<<PREP_XB + PREP_QB + PREP_PB, 256>>>(x, w_qkv, w_proj,
                                                   xh, xl, wqh, wql, wph, wpl);

    // 1) QKV projection (tensor cores): [8192,256] @ [256,768] + b
    {
        dim3 grid(C3 / 64, NPIX / 128);
        gemm_mma<<<grid, 128, GT_SMEM>>>(xh, xl, wqh, wql, b_qkv, qkv, C3, CC);
    }

    // 2) Neighborhood attention (fp16 K/V smem; emits bf16 hi/lo)
    {
        const int smem = 2 * 14 * 14 * 8 * (int)sizeof(h2x2);  // 25088 B
        dim3 grid(WW / 8, HH / 8, NH);
        na_attn<<<grid, 256, smem>>>(qkv, ath, atl);
    }

    // 3) Output projection (tensor cores): [8192,256] @ [256,256] + b
    {
        dim3 grid(CC / 64, NPIX / 128);
        gemm_mma<<<grid, 128, GT_SMEM>>>(ath, atl, wph, wpl, b_proj, out, CC, CC);
    }
}